// round 8
// baseline (speedup 1.0000x reference)
#include <cuda_runtime.h>

#define BB 16
#define HH 1024
#define WW 1280

// Per-batch coefficients:
// [0..8]   M   (3x3, row-major)        : K R^T K^-1
// [9..11]  Wv  (3)                     : K R^T (-t)
// [12..14] M2 row 2 (3)                : row 2 of (K R) K^-1
// [15]     W2z                         : (K t)[2]
__device__ float g_coef[BB][16];

__global__ void precompute_kernel(const float* __restrict__ trans,
                                  const float* __restrict__ rot,
                                  const float* __restrict__ intr) {
    int b = threadIdx.x;
    if (b >= BB) return;

    float K[3][3];
    #pragma unroll
    for (int i = 0; i < 3; i++)
        #pragma unroll
        for (int j = 0; j < 3; j++)
            K[i][j] = intr[i * 3 + j];

    float a00 = K[1][1]*K[2][2] - K[1][2]*K[2][1];
    float a01 = K[0][2]*K[2][1] - K[0][1]*K[2][2];
    float a02 = K[0][1]*K[1][2] - K[0][2]*K[1][1];
    float a10 = K[1][2]*K[2][0] - K[1][0]*K[2][2];
    float a11 = K[0][0]*K[2][2] - K[0][2]*K[2][0];
    float a12 = K[0][2]*K[1][0] - K[0][0]*K[1][2];
    float a20 = K[1][0]*K[2][1] - K[1][1]*K[2][0];
    float a21 = K[0][1]*K[2][0] - K[0][0]*K[2][1];
    float a22 = K[0][0]*K[1][1] - K[0][1]*K[1][0];
    float det = K[0][0]*a00 + K[0][1]*a10 + K[0][2]*a20;
    float id  = 1.0f / det;
    float Ki[3][3] = {{a00*id, a01*id, a02*id},
                      {a10*id, a11*id, a12*id},
                      {a20*id, a21*id, a22*id}};

    float R[3][3];
    #pragma unroll
    for (int i = 0; i < 3; i++)
        #pragma unroll
        for (int j = 0; j < 3; j++)
            R[i][j] = rot[b * 9 + i * 3 + j];

    float t0 = trans[b * 3 + 0], t1 = trans[b * 3 + 1], t2 = trans[b * 3 + 2];

    // temp = K * R^T
    float T[3][3];
    #pragma unroll
    for (int i = 0; i < 3; i++)
        #pragma unroll
        for (int k = 0; k < 3; k++)
            T[i][k] = K[i][0]*R[k][0] + K[i][1]*R[k][1] + K[i][2]*R[k][2];

    float Wv[3];
    #pragma unroll
    for (int i = 0; i < 3; i++)
        Wv[i] = -(T[i][0]*t0 + T[i][1]*t1 + T[i][2]*t2);

    float M[3][3];
    #pragma unroll
    for (int i = 0; i < 3; i++)
        #pragma unroll
        for (int k = 0; k < 3; k++)
            M[i][k] = T[i][0]*Ki[0][k] + T[i][1]*Ki[1][k] + T[i][2]*Ki[2][k];

    float KR2[3];
    #pragma unroll
    for (int k = 0; k < 3; k++)
        KR2[k] = K[2][0]*R[0][k] + K[2][1]*R[1][k] + K[2][2]*R[2][k];
    float M2r[3];
    #pragma unroll
    for (int k = 0; k < 3; k++)
        M2r[k] = KR2[0]*Ki[0][k] + KR2[1]*Ki[1][k] + KR2[2]*Ki[2][k];

    float W2z = K[2][0]*t0 + K[2][1]*t1 + K[2][2]*t2;

    float* c = g_coef[b];
    c[0] = M[0][0]; c[1] = M[0][1]; c[2] = M[0][2];
    c[3] = M[1][0]; c[4] = M[1][1]; c[5] = M[1][2];
    c[6] = M[2][0]; c[7] = M[2][1]; c[8] = M[2][2];
    c[9] = Wv[0];   c[10] = Wv[1];  c[11] = Wv[2];
    c[12] = M2r[0]; c[13] = M2r[1]; c[14] = M2r[2];
    c[15] = W2z;
}

// select element idx (0..3) from a float4 with pure SELs (no local mem)
__device__ __forceinline__ float sel4(const float4& v, int idx) {
    float lo = (idx & 1) ? v.y : v.x;
    float hi = (idx & 1) ? v.w : v.z;
    return (idx & 2) ? hi : lo;
}

// Layout: each warp owns a contiguous 128-pixel span within one image row
// (WW=1280 divisible by 128). Thread t handles pixels span+t+32*i, i=0..3.
// Gather strategy: per corner-row, ONE aligned float4 LDG.128 at (ix0c & ~3)
// covers both x-corners with prob 3/4; predicated scalar fixup when ix1c
// falls past the quad (prob ~1/4). Wavefronts/LDG = distinct 128B lines, so
// this cuts gather wavefronts ~4S -> ~2.5S per iteration.
__global__ void __launch_bounds__(256)
depth_warp_kernel(const float* __restrict__ d1,
                  const float* __restrict__ d2,
                  float* __restrict__ out) {
    const int lane = threadIdx.x & 31;
    const int wid  = threadIdx.x >> 5;
    const int warp_global = blockIdx.x * 8 + wid;
    const int span = warp_global * 128;

    const int x0 = span % WW;
    const int y  = (span / WW) & (HH - 1);
    const int b  = span / (WW * HH);

    const float* c = g_coef[b];
    const float m00 = c[0], m01 = c[1], m02 = c[2];
    const float m10 = c[3], m11 = c[4], m12 = c[5];
    const float m20 = c[6], m21 = c[7], m22 = c[8];
    const float wv0 = c[9], wv1 = c[10], wv2 = c[11];
    const float q20 = c[12], q21 = c[13], q22 = c[14];
    const float w2z = c[15];

    const float* d2b = d2 + b * (HH * WW);

    const float fv = (float)y;
    const float ry0 = fmaf(m01, fv, m02);
    const float ry1 = fmaf(m11, fv, m12);
    const float ry2 = fmaf(m21, fv, m22);

    const int base = span + lane;

    // ---- phase A: project all 4 pixels ----
    float u2a[4], v2a[4];
    #pragma unroll
    for (int i = 0; i < 4; i++) {
        const float z1 = __ldg(d1 + base + 32 * i);
        const float fu = (float)(x0 + lane + 32 * i);
        const float z2 = fmaf(z1, fmaf(m20, fu, ry2), wv2);
        const float nu = fmaf(z1, fmaf(m00, fu, ry0), wv0);
        const float nv = fmaf(z1, fmaf(m10, fu, ry1), wv1);
        const float inv = __fdividef(1.0f, z2);
        u2a[i] = nu * inv;
        v2a[i] = nv * inv;
    }

    // ---- phase B: issue all gathers (2x LDG.128 + predicated fixups) ----
    float4 r0v[4], r1v[4];
    float ex0[4], ex1[4];
    #pragma unroll
    for (int i = 0; i < 4; i++) {
        const int ix0 = __float2int_rd(u2a[i]);
        const int iy0 = __float2int_rd(v2a[i]);
        const int ix1c = min(max(ix0 + 1, 0), WW - 1);
        const int ix0c = min(max(ix0, 0), WW - 1);
        const int iy1c = min(max(iy0 + 1, 0), HH - 1);
        const int iy0c = min(max(iy0, 0), HH - 1);
        const int a4 = ix0c & ~3;

        const float* row0 = d2b + iy0c * WW;
        const float* row1 = d2b + iy1c * WW;
        r0v[i] = __ldg(reinterpret_cast<const float4*>(row0 + a4));
        r1v[i] = __ldg(reinterpret_cast<const float4*>(row1 + a4));

        ex0[i] = 0.0f; ex1[i] = 0.0f;
        if (ix1c - a4 > 3) {                 // predicated: ~1/4 of lanes
            ex0[i] = __ldg(row0 + ix1c);
            ex1[i] = __ldg(row1 + ix1c);
        }
    }

    // ---- phase C: select corners, weights, combine, store ----
    #pragma unroll
    for (int i = 0; i < 4; i++) {
        const float u2 = u2a[i];
        const float v2 = v2a[i];
        const int ix0 = __float2int_rd(u2);
        const int iy0 = __float2int_rd(v2);
        const int ix1c = min(max(ix0 + 1, 0), WW - 1);
        const int ix0c = min(max(ix0, 0), WW - 1);
        const int iy1c = min(max(iy0 + 1, 0), HH - 1);
        const int iy0c = min(max(iy0, 0), HH - 1);
        const int a4 = ix0c & ~3;

        const int ia = ix0c & 3;             // 0..3 within quad
        const int ic = ix1c - a4;            // 0..4

        const float Da = sel4(r0v[i], ia);
        const float Db = sel4(r1v[i], ia);
        const float Dc = (ic > 3) ? ex0[i] : sel4(r0v[i], ic);
        const float Dd = (ic > 3) ? ex1[i] : sel4(r1v[i], ic);

        const float x0f = (float)ix0c, x1f = (float)ix1c;
        const float y0f = (float)iy0c, y1f = (float)iy1c;

        const float wa = (x1f - u2) * (y1f - v2);
        const float wb = (x1f - u2) * (v2 - y0f);
        const float wc = (u2 - x0f) * (y1f - v2);
        const float wd = (u2 - x0f) * (v2 - y0f);

        // d1_calc at each corner: w2z + d2 * (q20*ix + q21*iy + q22)
        const float rp0 = fmaf(q21, y0f, q22);
        const float rp1 = fmaf(q21, y1f, q22);
        const float px0 = q20 * x0f;
        const float px1 = q20 * x1f;

        const float Ia = fmaf(Da, px0 + rp0, w2z);
        const float Ib = fmaf(Db, px0 + rp1, w2z);
        const float Ic = fmaf(Dc, px1 + rp0, w2z);
        const float Id = fmaf(Dd, px1 + rp1, w2z);

        out[base + 32 * i] = wa * Ia + wb * Ib + wc * Ic + wd * Id;
    }
}

extern "C" void kernel_launch(void* const* d_in, const int* in_sizes, int n_in,
                              void* d_out, int out_size) {
    const float* d1   = (const float*)d_in[0];
    const float* d2   = (const float*)d_in[1];
    const float* tr   = (const float*)d_in[2];
    const float* rot  = (const float*)d_in[3];
    const float* intr = (const float*)d_in[4];
    float* out = (float*)d_out;

    precompute_kernel<<<1, BB>>>(tr, rot, intr);

    const int total = BB * HH * WW;                    // 20,971,520
    const int blocks = total / 1024;                   // 8 warps * 128 px per block
    depth_warp_kernel<<<blocks, 256>>>(d1, d2, out);
}

// round 9
// speedup vs baseline: 1.1418x; 1.1418x over previous
#include <cuda_runtime.h>

#define BB 16
#define HH 1024
#define WW 1280

// Per-batch coefficients:
// [0..8]   M   (3x3, row-major)        : K R^T K^-1
// [9..11]  Wv  (3)                     : K R^T (-t)
// [12..14] M2 row 2 (3)                : row 2 of (K R) K^-1
// [15]     W2z                         : (K t)[2]
__device__ float g_coef[BB][16];

__global__ void precompute_kernel(const float* __restrict__ trans,
                                  const float* __restrict__ rot,
                                  const float* __restrict__ intr) {
    int b = threadIdx.x;
    if (b >= BB) return;

    float K[3][3];
    #pragma unroll
    for (int i = 0; i < 3; i++)
        #pragma unroll
        for (int j = 0; j < 3; j++)
            K[i][j] = intr[i * 3 + j];

    float a00 = K[1][1]*K[2][2] - K[1][2]*K[2][1];
    float a01 = K[0][2]*K[2][1] - K[0][1]*K[2][2];
    float a02 = K[0][1]*K[1][2] - K[0][2]*K[1][1];
    float a10 = K[1][2]*K[2][0] - K[1][0]*K[2][2];
    float a11 = K[0][0]*K[2][2] - K[0][2]*K[2][0];
    float a12 = K[0][2]*K[1][0] - K[0][0]*K[1][2];
    float a20 = K[1][0]*K[2][1] - K[1][1]*K[2][0];
    float a21 = K[0][1]*K[2][0] - K[0][0]*K[2][1];
    float a22 = K[0][0]*K[1][1] - K[0][1]*K[1][0];
    float det = K[0][0]*a00 + K[0][1]*a10 + K[0][2]*a20;
    float id  = 1.0f / det;
    float Ki[3][3] = {{a00*id, a01*id, a02*id},
                      {a10*id, a11*id, a12*id},
                      {a20*id, a21*id, a22*id}};

    float R[3][3];
    #pragma unroll
    for (int i = 0; i < 3; i++)
        #pragma unroll
        for (int j = 0; j < 3; j++)
            R[i][j] = rot[b * 9 + i * 3 + j];

    float t0 = trans[b * 3 + 0], t1 = trans[b * 3 + 1], t2 = trans[b * 3 + 2];

    // temp = K * R^T
    float T[3][3];
    #pragma unroll
    for (int i = 0; i < 3; i++)
        #pragma unroll
        for (int k = 0; k < 3; k++)
            T[i][k] = K[i][0]*R[k][0] + K[i][1]*R[k][1] + K[i][2]*R[k][2];

    float Wv[3];
    #pragma unroll
    for (int i = 0; i < 3; i++)
        Wv[i] = -(T[i][0]*t0 + T[i][1]*t1 + T[i][2]*t2);

    float M[3][3];
    #pragma unroll
    for (int i = 0; i < 3; i++)
        #pragma unroll
        for (int k = 0; k < 3; k++)
            M[i][k] = T[i][0]*Ki[0][k] + T[i][1]*Ki[1][k] + T[i][2]*Ki[2][k];

    float KR2[3];
    #pragma unroll
    for (int k = 0; k < 3; k++)
        KR2[k] = K[2][0]*R[0][k] + K[2][1]*R[1][k] + K[2][2]*R[2][k];
    float M2r[3];
    #pragma unroll
    for (int k = 0; k < 3; k++)
        M2r[k] = KR2[0]*Ki[0][k] + KR2[1]*Ki[1][k] + KR2[2]*Ki[2][k];

    float W2z = K[2][0]*t0 + K[2][1]*t1 + K[2][2]*t2;

    float* c = g_coef[b];
    c[0] = M[0][0]; c[1] = M[0][1]; c[2] = M[0][2];
    c[3] = M[1][0]; c[4] = M[1][1]; c[5] = M[1][2];
    c[6] = M[2][0]; c[7] = M[2][1]; c[8] = M[2][2];
    c[9] = Wv[0];   c[10] = Wv[1];  c[11] = Wv[2];
    c[12] = M2r[0]; c[13] = M2r[1]; c[14] = M2r[2];
    c[15] = W2z;
}

// Layout: each warp owns a contiguous 128-pixel span within one image row
// (WW=1280 divisible by 128). Thread t handles pixels span+t+32*i, i=0..3.
// Phase B issues all 16 scalar gather LDGs (scalar = optimal for scattered
// lanes); u2/v2 are NOT kept live across phase B — phase C reloads z1
// (L1 hit) and recomputes the projection, cutting ~8 live registers to
// raise occupancy.
__global__ void __launch_bounds__(256)
depth_warp_kernel(const float* __restrict__ d1,
                  const float* __restrict__ d2,
                  float* __restrict__ out) {
    const int lane = threadIdx.x & 31;
    const int wid  = threadIdx.x >> 5;
    const int warp_global = blockIdx.x * 8 + wid;
    const int span = warp_global * 128;

    const int x0 = span % WW;
    const int y  = (span / WW) & (HH - 1);
    const int b  = span / (WW * HH);

    const float* c = g_coef[b];
    const float m00 = c[0], m01 = c[1], m02 = c[2];
    const float m10 = c[3], m11 = c[4], m12 = c[5];
    const float m20 = c[6], m21 = c[7], m22 = c[8];
    const float wv0 = c[9], wv1 = c[10], wv2 = c[11];
    const float q20 = c[12], q21 = c[13], q22 = c[14];
    const float w2z = c[15];

    const float* d2b = d2 + b * (HH * WW);

    const float fv = (float)y;
    const float ry0 = fmaf(m01, fv, m02);
    const float ry1 = fmaf(m11, fv, m12);
    const float ry2 = fmaf(m21, fv, m22);

    const int base = span + lane;

    // ---- phase A+B: project and issue all 16 gathers; keep only D regs ----
    float Da[4], Db[4], Dc[4], Dd[4];
    #pragma unroll
    for (int i = 0; i < 4; i++) {
        const float z1 = __ldg(d1 + base + 32 * i);
        const float fu = (float)(x0 + lane + 32 * i);
        const float z2 = fmaf(z1, fmaf(m20, fu, ry2), wv2);
        const float nu = fmaf(z1, fmaf(m00, fu, ry0), wv0);
        const float nv = fmaf(z1, fmaf(m10, fu, ry1), wv1);
        const float inv = __fdividef(1.0f, z2);
        const float u2 = nu * inv;
        const float v2 = nv * inv;

        const int ix0 = __float2int_rd(u2);
        const int iy0 = __float2int_rd(v2);
        const int ix1c = min(max(ix0 + 1, 0), WW - 1);
        const int ix0c = min(max(ix0, 0), WW - 1);
        const int iy1c = min(max(iy0 + 1, 0), HH - 1);
        const int iy0c = min(max(iy0, 0), HH - 1);
        const float* row0 = d2b + iy0c * WW;
        const float* row1 = d2b + iy1c * WW;
        Da[i] = __ldg(row0 + ix0c);
        Db[i] = __ldg(row1 + ix0c);
        Dc[i] = __ldg(row0 + ix1c);
        Dd[i] = __ldg(row1 + ix1c);
    }

    // ---- phase C: reload z1 (L1 hit), recompute projection, combine ----
    #pragma unroll
    for (int i = 0; i < 4; i++) {
        const float z1 = __ldg(d1 + base + 32 * i);
        const float fu = (float)(x0 + lane + 32 * i);
        const float z2 = fmaf(z1, fmaf(m20, fu, ry2), wv2);
        const float nu = fmaf(z1, fmaf(m00, fu, ry0), wv0);
        const float nv = fmaf(z1, fmaf(m10, fu, ry1), wv1);
        const float inv = __fdividef(1.0f, z2);
        const float u2 = nu * inv;
        const float v2 = nv * inv;

        const int ix0 = __float2int_rd(u2);
        const int iy0 = __float2int_rd(v2);
        const int ix1c = min(max(ix0 + 1, 0), WW - 1);
        const int ix0c = min(max(ix0, 0), WW - 1);
        const int iy1c = min(max(iy0 + 1, 0), HH - 1);
        const int iy0c = min(max(iy0, 0), HH - 1);

        const float x0f = (float)ix0c, x1f = (float)ix1c;
        const float y0f = (float)iy0c, y1f = (float)iy1c;

        const float wa = (x1f - u2) * (y1f - v2);
        const float wb = (x1f - u2) * (v2 - y0f);
        const float wc = (u2 - x0f) * (y1f - v2);
        const float wd = (u2 - x0f) * (v2 - y0f);

        // d1_calc at each corner: w2z + d2 * (q20*ix + q21*iy + q22)
        const float rp0 = fmaf(q21, y0f, q22);
        const float rp1 = fmaf(q21, y1f, q22);
        const float px0 = q20 * x0f;
        const float px1 = q20 * x1f;

        const float Ia = fmaf(Da[i], px0 + rp0, w2z);
        const float Ib = fmaf(Db[i], px0 + rp1, w2z);
        const float Ic = fmaf(Dc[i], px1 + rp0, w2z);
        const float Id = fmaf(Dd[i], px1 + rp1, w2z);

        out[base + 32 * i] = wa * Ia + wb * Ib + wc * Ic + wd * Id;
    }
}

extern "C" void kernel_launch(void* const* d_in, const int* in_sizes, int n_in,
                              void* d_out, int out_size) {
    const float* d1   = (const float*)d_in[0];
    const float* d2   = (const float*)d_in[1];
    const float* tr   = (const float*)d_in[2];
    const float* rot  = (const float*)d_in[3];
    const float* intr = (const float*)d_in[4];
    float* out = (float*)d_out;

    precompute_kernel<<<1, BB>>>(tr, rot, intr);

    const int total = BB * HH * WW;                    // 20,971,520
    const int blocks = total / 1024;                   // 8 warps * 128 px per block
    depth_warp_kernel<<<blocks, 256>>>(d1, d2, out);
}

// round 12
// speedup vs baseline: 1.2969x; 1.1359x over previous
#include <cuda_runtime.h>

#define BB 16
#define HH 1024
#define WW 1280

// Per-batch coefficients:
// [0..8]   M   (3x3, row-major)        : K R^T K^-1
// [9..11]  Wv  (3)                     : K R^T (-t)
// [12..14] M2 row 2 (3)                : row 2 of (K R) K^-1
// [15]     W2z                         : (K t)[2]
__device__ float g_coef[BB][16];

__global__ void precompute_kernel(const float* __restrict__ trans,
                                  const float* __restrict__ rot,
                                  const float* __restrict__ intr) {
    int b = threadIdx.x;
    if (b >= BB) return;

    float K[3][3];
    #pragma unroll
    for (int i = 0; i < 3; i++)
        #pragma unroll
        for (int j = 0; j < 3; j++)
            K[i][j] = intr[i * 3 + j];

    float a00 = K[1][1]*K[2][2] - K[1][2]*K[2][1];
    float a01 = K[0][2]*K[2][1] - K[0][1]*K[2][2];
    float a02 = K[0][1]*K[1][2] - K[0][2]*K[1][1];
    float a10 = K[1][2]*K[2][0] - K[1][0]*K[2][2];
    float a11 = K[0][0]*K[2][2] - K[0][2]*K[2][0];
    float a12 = K[0][2]*K[1][0] - K[0][0]*K[1][2];
    float a20 = K[1][0]*K[2][1] - K[1][1]*K[2][0];
    float a21 = K[0][1]*K[2][0] - K[0][0]*K[2][1];
    float a22 = K[0][0]*K[1][1] - K[0][1]*K[1][0];
    float det = K[0][0]*a00 + K[0][1]*a10 + K[0][2]*a20;
    float id  = 1.0f / det;
    float Ki[3][3] = {{a00*id, a01*id, a02*id},
                      {a10*id, a11*id, a12*id},
                      {a20*id, a21*id, a22*id}};

    float R[3][3];
    #pragma unroll
    for (int i = 0; i < 3; i++)
        #pragma unroll
        for (int j = 0; j < 3; j++)
            R[i][j] = rot[b * 9 + i * 3 + j];

    float t0 = trans[b * 3 + 0], t1 = trans[b * 3 + 1], t2 = trans[b * 3 + 2];

    // temp = K * R^T
    float T[3][3];
    #pragma unroll
    for (int i = 0; i < 3; i++)
        #pragma unroll
        for (int k = 0; k < 3; k++)
            T[i][k] = K[i][0]*R[k][0] + K[i][1]*R[k][1] + K[i][2]*R[k][2];

    float Wv[3];
    #pragma unroll
    for (int i = 0; i < 3; i++)
        Wv[i] = -(T[i][0]*t0 + T[i][1]*t1 + T[i][2]*t2);

    float M[3][3];
    #pragma unroll
    for (int i = 0; i < 3; i++)
        #pragma unroll
        for (int k = 0; k < 3; k++)
            M[i][k] = T[i][0]*Ki[0][k] + T[i][1]*Ki[1][k] + T[i][2]*Ki[2][k];

    float KR2[3];
    #pragma unroll
    for (int k = 0; k < 3; k++)
        KR2[k] = K[2][0]*R[0][k] + K[2][1]*R[1][k] + K[2][2]*R[2][k];
    float M2r[3];
    #pragma unroll
    for (int k = 0; k < 3; k++)
        M2r[k] = KR2[0]*Ki[0][k] + KR2[1]*Ki[1][k] + KR2[2]*Ki[2][k];

    float W2z = K[2][0]*t0 + K[2][1]*t1 + K[2][2]*t2;

    float* c = g_coef[b];
    c[0] = M[0][0]; c[1] = M[0][1]; c[2] = M[0][2];
    c[3] = M[1][0]; c[4] = M[1][1]; c[5] = M[1][2];
    c[6] = M[2][0]; c[7] = M[2][1]; c[8] = M[2][2];
    c[9] = Wv[0];   c[10] = Wv[1];  c[11] = Wv[2];
    c[12] = M2r[0]; c[13] = M2r[1]; c[14] = M2r[2];
    c[15] = W2z;
}

// Layout: each warp owns a contiguous 128-pixel span within one image row
// (WW=1280 divisible by 128). Thread t handles pixels span+t+32*i, i=0..3.
// Software pipeline: (A) project all 4 pixels, (B) issue all 16 scalar
// gather LDGs (scalar = optimal for scattered lanes), (C) weights+combine.
// __launch_bounds__(256, 7) caps regs at 36 -> 7 blocks/SM (56 warps, ~87%
// occ) for more outstanding gathers against the L1 service queue.
__global__ void __launch_bounds__(256, 7)
depth_warp_kernel(const float* __restrict__ d1,
                  const float* __restrict__ d2,
                  float* __restrict__ out) {
    const int lane = threadIdx.x & 31;
    const int wid  = threadIdx.x >> 5;
    const int warp_global = blockIdx.x * 8 + wid;
    const int span = warp_global * 128;

    const int x0 = span % WW;
    const int y  = (span / WW) & (HH - 1);
    const int b  = span / (WW * HH);

    const float* c = g_coef[b];
    const float m00 = c[0], m01 = c[1], m02 = c[2];
    const float m10 = c[3], m11 = c[4], m12 = c[5];
    const float m20 = c[6], m21 = c[7], m22 = c[8];
    const float wv0 = c[9], wv1 = c[10], wv2 = c[11];
    const float q20 = c[12], q21 = c[13], q22 = c[14];
    const float w2z = c[15];

    const float* d2b = d2 + b * (HH * WW);

    const float fv = (float)y;
    const float ry0 = fmaf(m01, fv, m02);
    const float ry1 = fmaf(m11, fv, m12);
    const float ry2 = fmaf(m21, fv, m22);

    const int base = span + lane;

    // ---- phase A: project ----
    float u2a[4], v2a[4];
    #pragma unroll
    for (int i = 0; i < 4; i++) {
        const float z1 = __ldg(d1 + base + 32 * i);
        const float fu = (float)(x0 + lane + 32 * i);
        const float z2 = fmaf(z1, fmaf(m20, fu, ry2), wv2);
        const float nu = fmaf(z1, fmaf(m00, fu, ry0), wv0);
        const float nv = fmaf(z1, fmaf(m10, fu, ry1), wv1);
        const float inv = __fdividef(1.0f, z2);
        u2a[i] = nu * inv;
        v2a[i] = nv * inv;
    }

    // ---- phase B: issue all 16 gathers ----
    float Da[4], Db[4], Dc[4], Dd[4];
    #pragma unroll
    for (int i = 0; i < 4; i++) {
        const int ix0 = __float2int_rd(u2a[i]);
        const int iy0 = __float2int_rd(v2a[i]);
        const int ix1c = min(max(ix0 + 1, 0), WW - 1);
        const int ix0c = min(max(ix0, 0), WW - 1);
        const int iy1c = min(max(iy0 + 1, 0), HH - 1);
        const int iy0c = min(max(iy0, 0), HH - 1);
        const float* row0 = d2b + iy0c * WW;
        const float* row1 = d2b + iy1c * WW;
        Da[i] = __ldg(row0 + ix0c);
        Db[i] = __ldg(row1 + ix0c);
        Dc[i] = __ldg(row0 + ix1c);
        Dd[i] = __ldg(row1 + ix1c);
    }

    // ---- phase C: weights + combine + store ----
    #pragma unroll
    for (int i = 0; i < 4; i++) {
        const float u2 = u2a[i];
        const float v2 = v2a[i];
        const int ix0 = __float2int_rd(u2);
        const int iy0 = __float2int_rd(v2);
        const int ix1c = min(max(ix0 + 1, 0), WW - 1);
        const int ix0c = min(max(ix0, 0), WW - 1);
        const int iy1c = min(max(iy0 + 1, 0), HH - 1);
        const int iy0c = min(max(iy0, 0), HH - 1);

        const float x0f = (float)ix0c, x1f = (float)ix1c;
        const float y0f = (float)iy0c, y1f = (float)iy1c;

        const float wa = (x1f - u2) * (y1f - v2);
        const float wb = (x1f - u2) * (v2 - y0f);
        const float wc = (u2 - x0f) * (y1f - v2);
        const float wd = (u2 - x0f) * (v2 - y0f);

        // d1_calc at each corner: w2z + d2 * (q20*ix + q21*iy + q22)
        const float rp0 = fmaf(q21, y0f, q22);
        const float rp1 = fmaf(q21, y1f, q22);
        const float px0 = q20 * x0f;
        const float px1 = q20 * x1f;

        const float Ia = fmaf(Da[i], px0 + rp0, w2z);
        const float Ib = fmaf(Db[i], px0 + rp1, w2z);
        const float Ic = fmaf(Dc[i], px1 + rp0, w2z);
        const float Id = fmaf(Dd[i], px1 + rp1, w2z);

        out[base + 32 * i] = wa * Ia + wb * Ib + wc * Ic + wd * Id;
    }
}

extern "C" void kernel_launch(void* const* d_in, const int* in_sizes, int n_in,
                              void* d_out, int out_size) {
    const float* d1   = (const float*)d_in[0];
    const float* d2   = (const float*)d_in[1];
    const float* tr   = (const float*)d_in[2];
    const float* rot  = (const float*)d_in[3];
    const float* intr = (const float*)d_in[4];
    float* out = (float*)d_out;

    precompute_kernel<<<1, BB>>>(tr, rot, intr);

    const int total = BB * HH * WW;                    // 20,971,520
    const int blocks = total / 1024;                   // 8 warps * 128 px per block
    depth_warp_kernel<<<blocks, 256>>>(d1, d2, out);
}

// round 13
// speedup vs baseline: 1.3310x; 1.0263x over previous
#include <cuda_runtime.h>

#define BB 16
#define HH 1024
#define WW 1280

// Per-batch coefficients:
// [0..8]   M   (3x3, row-major)        : K R^T K^-1
// [9..11]  Wv  (3)                     : K R^T (-t)
// [12..14] M2 row 2 (3)                : row 2 of (K R) K^-1
// [15]     W2z                         : (K t)[2]
__device__ float g_coef[BB][16];

__global__ void precompute_kernel(const float* __restrict__ trans,
                                  const float* __restrict__ rot,
                                  const float* __restrict__ intr) {
    int b = threadIdx.x;
    if (b >= BB) return;

    float K[3][3];
    #pragma unroll
    for (int i = 0; i < 3; i++)
        #pragma unroll
        for (int j = 0; j < 3; j++)
            K[i][j] = intr[i * 3 + j];

    float a00 = K[1][1]*K[2][2] - K[1][2]*K[2][1];
    float a01 = K[0][2]*K[2][1] - K[0][1]*K[2][2];
    float a02 = K[0][1]*K[1][2] - K[0][2]*K[1][1];
    float a10 = K[1][2]*K[2][0] - K[1][0]*K[2][2];
    float a11 = K[0][0]*K[2][2] - K[0][2]*K[2][0];
    float a12 = K[0][2]*K[1][0] - K[0][0]*K[1][2];
    float a20 = K[1][0]*K[2][1] - K[1][1]*K[2][0];
    float a21 = K[0][1]*K[2][0] - K[0][0]*K[2][1];
    float a22 = K[0][0]*K[1][1] - K[0][1]*K[1][0];
    float det = K[0][0]*a00 + K[0][1]*a10 + K[0][2]*a20;
    float id  = 1.0f / det;
    float Ki[3][3] = {{a00*id, a01*id, a02*id},
                      {a10*id, a11*id, a12*id},
                      {a20*id, a21*id, a22*id}};

    float R[3][3];
    #pragma unroll
    for (int i = 0; i < 3; i++)
        #pragma unroll
        for (int j = 0; j < 3; j++)
            R[i][j] = rot[b * 9 + i * 3 + j];

    float t0 = trans[b * 3 + 0], t1 = trans[b * 3 + 1], t2 = trans[b * 3 + 2];

    // temp = K * R^T
    float T[3][3];
    #pragma unroll
    for (int i = 0; i < 3; i++)
        #pragma unroll
        for (int k = 0; k < 3; k++)
            T[i][k] = K[i][0]*R[k][0] + K[i][1]*R[k][1] + K[i][2]*R[k][2];

    float Wv[3];
    #pragma unroll
    for (int i = 0; i < 3; i++)
        Wv[i] = -(T[i][0]*t0 + T[i][1]*t1 + T[i][2]*t2);

    float M[3][3];
    #pragma unroll
    for (int i = 0; i < 3; i++)
        #pragma unroll
        for (int k = 0; k < 3; k++)
            M[i][k] = T[i][0]*Ki[0][k] + T[i][1]*Ki[1][k] + T[i][2]*Ki[2][k];

    float KR2[3];
    #pragma unroll
    for (int k = 0; k < 3; k++)
        KR2[k] = K[2][0]*R[0][k] + K[2][1]*R[1][k] + K[2][2]*R[2][k];
    float M2r[3];
    #pragma unroll
    for (int k = 0; k < 3; k++)
        M2r[k] = KR2[0]*Ki[0][k] + KR2[1]*Ki[1][k] + KR2[2]*Ki[2][k];

    float W2z = K[2][0]*t0 + K[2][1]*t1 + K[2][2]*t2;

    float* c = g_coef[b];
    c[0] = M[0][0]; c[1] = M[0][1]; c[2] = M[0][2];
    c[3] = M[1][0]; c[4] = M[1][1]; c[5] = M[1][2];
    c[6] = M[2][0]; c[7] = M[2][1]; c[8] = M[2][2];
    c[9] = Wv[0];   c[10] = Wv[1];  c[11] = Wv[2];
    c[12] = M2r[0]; c[13] = M2r[1]; c[14] = M2r[2];
    c[15] = W2z;
}

// Tile layout: each block owns a 128(x) x 8(y) tile; warp w takes row
// y0+w over the same 128-column span, thread t handles x0+t+32*i.
// Vertically-adjacent rows gather nearly identical d2 lines, so the 8
// warps' footprints overlap ~87% -> gather L1 hit rate jumps (fewer
// miss/fill/replay wavefronts on the binding l1tex pipe).
// Software pipeline: (A) project, (B) issue all 16 scalar gathers,
// (C) weights+combine. Scalar gathers = optimal for scattered lanes.
// __launch_bounds__(256, 7): 32 regs, 56 warps/SM.
__global__ void __launch_bounds__(256, 7)
depth_warp_kernel(const float* __restrict__ d1,
                  const float* __restrict__ d2,
                  float* __restrict__ out) {
    const int lane = threadIdx.x & 31;
    const int wid  = threadIdx.x >> 5;

    // block -> tile
    const int bid = blockIdx.x;
    const int tx  = bid % (WW / 128);              // 10 tiles in x
    const int ty  = (bid / (WW / 128)) % (HH / 8); // 128 tiles in y
    const int b   = bid / ((WW / 128) * (HH / 8)); // batch

    const int x0 = tx * 128;
    const int y  = ty * 8 + wid;

    const float* c = g_coef[b];
    const float m00 = c[0], m01 = c[1], m02 = c[2];
    const float m10 = c[3], m11 = c[4], m12 = c[5];
    const float m20 = c[6], m21 = c[7], m22 = c[8];
    const float wv0 = c[9], wv1 = c[10], wv2 = c[11];
    const float q20 = c[12], q21 = c[13], q22 = c[14];
    const float w2z = c[15];

    const float* d2b = d2 + b * (HH * WW);

    const float fv = (float)y;
    const float ry0 = fmaf(m01, fv, m02);
    const float ry1 = fmaf(m11, fv, m12);
    const float ry2 = fmaf(m21, fv, m22);

    const int base = b * (HH * WW) + y * WW + x0 + lane;

    // ---- phase A: project ----
    float u2a[4], v2a[4];
    #pragma unroll
    for (int i = 0; i < 4; i++) {
        const float z1 = __ldg(d1 + base + 32 * i);
        const float fu = (float)(x0 + lane + 32 * i);
        const float z2 = fmaf(z1, fmaf(m20, fu, ry2), wv2);
        const float nu = fmaf(z1, fmaf(m00, fu, ry0), wv0);
        const float nv = fmaf(z1, fmaf(m10, fu, ry1), wv1);
        const float inv = __fdividef(1.0f, z2);
        u2a[i] = nu * inv;
        v2a[i] = nv * inv;
    }

    // ---- phase B: issue all 16 gathers ----
    float Da[4], Db[4], Dc[4], Dd[4];
    #pragma unroll
    for (int i = 0; i < 4; i++) {
        const int ix0 = __float2int_rd(u2a[i]);
        const int iy0 = __float2int_rd(v2a[i]);
        const int ix1c = min(max(ix0 + 1, 0), WW - 1);
        const int ix0c = min(max(ix0, 0), WW - 1);
        const int iy1c = min(max(iy0 + 1, 0), HH - 1);
        const int iy0c = min(max(iy0, 0), HH - 1);
        const float* row0 = d2b + iy0c * WW;
        const float* row1 = d2b + iy1c * WW;
        Da[i] = __ldg(row0 + ix0c);
        Db[i] = __ldg(row1 + ix0c);
        Dc[i] = __ldg(row0 + ix1c);
        Dd[i] = __ldg(row1 + ix1c);
    }

    // ---- phase C: weights + combine + store ----
    #pragma unroll
    for (int i = 0; i < 4; i++) {
        const float u2 = u2a[i];
        const float v2 = v2a[i];
        const int ix0 = __float2int_rd(u2);
        const int iy0 = __float2int_rd(v2);
        const int ix1c = min(max(ix0 + 1, 0), WW - 1);
        const int ix0c = min(max(ix0, 0), WW - 1);
        const int iy1c = min(max(iy0 + 1, 0), HH - 1);
        const int iy0c = min(max(iy0, 0), HH - 1);

        const float x0f = (float)ix0c, x1f = (float)ix1c;
        const float y0f = (float)iy0c, y1f = (float)iy1c;

        const float wa = (x1f - u2) * (y1f - v2);
        const float wb = (x1f - u2) * (v2 - y0f);
        const float wc = (u2 - x0f) * (y1f - v2);
        const float wd = (u2 - x0f) * (v2 - y0f);

        // d1_calc at each corner: w2z + d2 * (q20*ix + q21*iy + q22)
        const float rp0 = fmaf(q21, y0f, q22);
        const float rp1 = fmaf(q21, y1f, q22);
        const float px0 = q20 * x0f;
        const float px1 = q20 * x1f;

        const float Ia = fmaf(Da[i], px0 + rp0, w2z);
        const float Ib = fmaf(Db[i], px0 + rp1, w2z);
        const float Ic = fmaf(Dc[i], px1 + rp0, w2z);
        const float Id = fmaf(Dd[i], px1 + rp1, w2z);

        out[base + 32 * i] = wa * Ia + wb * Ib + wc * Ic + wd * Id;
    }
}

extern "C" void kernel_launch(void* const* d_in, const int* in_sizes, int n_in,
                              void* d_out, int out_size) {
    const float* d1   = (const float*)d_in[0];
    const float* d2   = (const float*)d_in[1];
    const float* tr   = (const float*)d_in[2];
    const float* rot  = (const float*)d_in[3];
    const float* intr = (const float*)d_in[4];
    float* out = (float*)d_out;

    precompute_kernel<<<1, BB>>>(tr, rot, intr);

    const int blocks = (WW / 128) * (HH / 8) * BB;     // 10*128*16 = 20480
    depth_warp_kernel<<<blocks, 256>>>(d1, d2, out);
}

// round 14
// speedup vs baseline: 1.3633x; 1.0242x over previous
#include <cuda_runtime.h>

#define BB 16
#define HH 1024
#define WW 1280

// Per-batch coefficients:
// [0..8]   M   (3x3, row-major)        : K R^T K^-1
// [9..11]  Wv  (3)                     : K R^T (-t)
// [12..14] M2 row 2 (3)                : row 2 of (K R) K^-1
// [15]     W2z                         : (K t)[2]
__device__ float g_coef[BB][16];

__global__ void precompute_kernel(const float* __restrict__ trans,
                                  const float* __restrict__ rot,
                                  const float* __restrict__ intr) {
    int b = threadIdx.x;
    if (b >= BB) return;

    float K[3][3];
    #pragma unroll
    for (int i = 0; i < 3; i++)
        #pragma unroll
        for (int j = 0; j < 3; j++)
            K[i][j] = intr[i * 3 + j];

    float a00 = K[1][1]*K[2][2] - K[1][2]*K[2][1];
    float a01 = K[0][2]*K[2][1] - K[0][1]*K[2][2];
    float a02 = K[0][1]*K[1][2] - K[0][2]*K[1][1];
    float a10 = K[1][2]*K[2][0] - K[1][0]*K[2][2];
    float a11 = K[0][0]*K[2][2] - K[0][2]*K[2][0];
    float a12 = K[0][2]*K[1][0] - K[0][0]*K[1][2];
    float a20 = K[1][0]*K[2][1] - K[1][1]*K[2][0];
    float a21 = K[0][1]*K[2][0] - K[0][0]*K[2][1];
    float a22 = K[0][0]*K[1][1] - K[0][1]*K[1][0];
    float det = K[0][0]*a00 + K[0][1]*a10 + K[0][2]*a20;
    float id  = 1.0f / det;
    float Ki[3][3] = {{a00*id, a01*id, a02*id},
                      {a10*id, a11*id, a12*id},
                      {a20*id, a21*id, a22*id}};

    float R[3][3];
    #pragma unroll
    for (int i = 0; i < 3; i++)
        #pragma unroll
        for (int j = 0; j < 3; j++)
            R[i][j] = rot[b * 9 + i * 3 + j];

    float t0 = trans[b * 3 + 0], t1 = trans[b * 3 + 1], t2 = trans[b * 3 + 2];

    // temp = K * R^T
    float T[3][3];
    #pragma unroll
    for (int i = 0; i < 3; i++)
        #pragma unroll
        for (int k = 0; k < 3; k++)
            T[i][k] = K[i][0]*R[k][0] + K[i][1]*R[k][1] + K[i][2]*R[k][2];

    float Wv[3];
    #pragma unroll
    for (int i = 0; i < 3; i++)
        Wv[i] = -(T[i][0]*t0 + T[i][1]*t1 + T[i][2]*t2);

    float M[3][3];
    #pragma unroll
    for (int i = 0; i < 3; i++)
        #pragma unroll
        for (int k = 0; k < 3; k++)
            M[i][k] = T[i][0]*Ki[0][k] + T[i][1]*Ki[1][k] + T[i][2]*Ki[2][k];

    float KR2[3];
    #pragma unroll
    for (int k = 0; k < 3; k++)
        KR2[k] = K[2][0]*R[0][k] + K[2][1]*R[1][k] + K[2][2]*R[2][k];
    float M2r[3];
    #pragma unroll
    for (int k = 0; k < 3; k++)
        M2r[k] = KR2[0]*Ki[0][k] + KR2[1]*Ki[1][k] + KR2[2]*Ki[2][k];

    float W2z = K[2][0]*t0 + K[2][1]*t1 + K[2][2]*t2;

    float* c = g_coef[b];
    c[0] = M[0][0]; c[1] = M[0][1]; c[2] = M[0][2];
    c[3] = M[1][0]; c[4] = M[1][1]; c[5] = M[1][2];
    c[6] = M[2][0]; c[7] = M[2][1]; c[8] = M[2][2];
    c[9] = Wv[0];   c[10] = Wv[1];  c[11] = Wv[2];
    c[12] = M2r[0]; c[13] = M2r[1]; c[14] = M2r[2];
    c[15] = W2z;
}

// Tile layout: each block owns a 128(x) x 8(y) tile; warp w takes row
// y0+w over the same 128-column span, thread t handles x0+t+32*i.
// Vertically-adjacent rows gather nearly identical d2 lines -> high L1
// hit rate (validated: L2 dropped 55%->29%).
// Software pipeline: (A) project, (B) issue all 16 scalar gathers
// (scalar = optimal for scattered lanes), (C) weights+combine.
// __launch_bounds__(256, 8): 32 regs, 2048 threads/SM = full occupancy.
__global__ void __launch_bounds__(256, 8)
depth_warp_kernel(const float* __restrict__ d1,
                  const float* __restrict__ d2,
                  float* __restrict__ out) {
    const int lane = threadIdx.x & 31;
    const int wid  = threadIdx.x >> 5;

    // block -> tile
    const int bid = blockIdx.x;
    const int tx  = bid % (WW / 128);              // 10 tiles in x
    const int ty  = (bid / (WW / 128)) % (HH / 8); // 128 tiles in y
    const int b   = bid / ((WW / 128) * (HH / 8)); // batch

    const int x0 = tx * 128;
    const int y  = ty * 8 + wid;

    const float* c = g_coef[b];
    const float m00 = c[0], m01 = c[1], m02 = c[2];
    const float m10 = c[3], m11 = c[4], m12 = c[5];
    const float m20 = c[6], m21 = c[7], m22 = c[8];
    const float wv0 = c[9], wv1 = c[10], wv2 = c[11];
    const float q20 = c[12], q21 = c[13], q22 = c[14];
    const float w2z = c[15];

    const float* d2b = d2 + b * (HH * WW);

    const float fv = (float)y;
    const float ry0 = fmaf(m01, fv, m02);
    const float ry1 = fmaf(m11, fv, m12);
    const float ry2 = fmaf(m21, fv, m22);

    const int base = b * (HH * WW) + y * WW + x0 + lane;

    // ---- phase A: project ----
    float u2a[4], v2a[4];
    #pragma unroll
    for (int i = 0; i < 4; i++) {
        const float z1 = __ldg(d1 + base + 32 * i);
        const float fu = (float)(x0 + lane + 32 * i);
        const float z2 = fmaf(z1, fmaf(m20, fu, ry2), wv2);
        const float nu = fmaf(z1, fmaf(m00, fu, ry0), wv0);
        const float nv = fmaf(z1, fmaf(m10, fu, ry1), wv1);
        const float inv = __fdividef(1.0f, z2);
        u2a[i] = nu * inv;
        v2a[i] = nv * inv;
    }

    // ---- phase B: issue all 16 gathers ----
    float Da[4], Db[4], Dc[4], Dd[4];
    #pragma unroll
    for (int i = 0; i < 4; i++) {
        const int ix0 = __float2int_rd(u2a[i]);
        const int iy0 = __float2int_rd(v2a[i]);
        const int ix1c = min(max(ix0 + 1, 0), WW - 1);
        const int ix0c = min(max(ix0, 0), WW - 1);
        const int iy1c = min(max(iy0 + 1, 0), HH - 1);
        const int iy0c = min(max(iy0, 0), HH - 1);
        const float* row0 = d2b + iy0c * WW;
        const float* row1 = d2b + iy1c * WW;
        Da[i] = __ldg(row0 + ix0c);
        Db[i] = __ldg(row1 + ix0c);
        Dc[i] = __ldg(row0 + ix1c);
        Dd[i] = __ldg(row1 + ix1c);
    }

    // ---- phase C: weights + combine + store ----
    #pragma unroll
    for (int i = 0; i < 4; i++) {
        const float u2 = u2a[i];
        const float v2 = v2a[i];
        const int ix0 = __float2int_rd(u2);
        const int iy0 = __float2int_rd(v2);
        const int ix1c = min(max(ix0 + 1, 0), WW - 1);
        const int ix0c = min(max(ix0, 0), WW - 1);
        const int iy1c = min(max(iy0 + 1, 0), HH - 1);
        const int iy0c = min(max(iy0, 0), HH - 1);

        const float x0f = (float)ix0c, x1f = (float)ix1c;
        const float y0f = (float)iy0c, y1f = (float)iy1c;

        const float wa = (x1f - u2) * (y1f - v2);
        const float wb = (x1f - u2) * (v2 - y0f);
        const float wc = (u2 - x0f) * (y1f - v2);
        const float wd = (u2 - x0f) * (v2 - y0f);

        // d1_calc at each corner: w2z + d2 * (q20*ix + q21*iy + q22)
        const float rp0 = fmaf(q21, y0f, q22);
        const float rp1 = fmaf(q21, y1f, q22);
        const float px0 = q20 * x0f;
        const float px1 = q20 * x1f;

        const float Ia = fmaf(Da[i], px0 + rp0, w2z);
        const float Ib = fmaf(Db[i], px0 + rp1, w2z);
        const float Ic = fmaf(Dc[i], px1 + rp0, w2z);
        const float Id = fmaf(Dd[i], px1 + rp1, w2z);

        out[base + 32 * i] = wa * Ia + wb * Ib + wc * Ic + wd * Id;
    }
}

extern "C" void kernel_launch(void* const* d_in, const int* in_sizes, int n_in,
                              void* d_out, int out_size) {
    const float* d1   = (const float*)d_in[0];
    const float* d2   = (const float*)d_in[1];
    const float* tr   = (const float*)d_in[2];
    const float* rot  = (const float*)d_in[3];
    const float* intr = (const float*)d_in[4];
    float* out = (float*)d_out;

    precompute_kernel<<<1, BB>>>(tr, rot, intr);

    const int blocks = (WW / 128) * (HH / 8) * BB;     // 10*128*16 = 20480
    depth_warp_kernel<<<blocks, 256>>>(d1, d2, out);
}